// round 2
// baseline (speedup 1.0000x reference)
#include <cuda_runtime.h>
#include <math.h>

#define T_STEPS 100
#define BATCH   256
#define IN_DIM  784
#define HID     1024
#define OUTD    10
#define P_DIM   64
#define ALPHA   0.05f   // DT / TAUM = 1e-3 / 0.02

// ---------------- scratch (static device globals; no runtime allocation) ----------------
__device__ float g_Iin[(size_t)T_STEPS * BATCH * HID];  // [t][b][h]  ~105 MB
__device__ float g_mem[BATCH * HID];
__device__ float g_th [BATCH * HID];                    // tanh(mem)
__device__ float g_rm [BATCH * HID];                    // running max of tanh(mem)
__device__ float g_U  [2][BATCH * P_DIM];               // double-buffered rank-64 bottleneck
__device__ float g_Wpl[HID * P_DIM];                    // pin * l

// ---------------- prep: Wpl = pin * l, zero state ----------------
__global__ void prep_kernel(const float* __restrict__ pin, const float* __restrict__ l) {
    int idx = blockIdx.x * blockDim.x + threadIdx.x;     // grid covers 262144
    if (idx < HID * P_DIM) g_Wpl[idx] = pin[idx] * l[idx & (P_DIM - 1)];
    if (idx < BATCH * HID) {
        g_mem[idx] = 0.0f;
        g_th[idx]  = 0.0f;
        g_rm[idx]  = -2.0f;   // tanh in (-1,1)
    }
    if (idx < 2 * BATCH * P_DIM) ((float*)g_U)[idx] = 0.0f;
}

// ---------------- big GEMM: Iin = spk @ Win^T  (M=25600, N=1024, K=784) ----------------
// C[m][n] = sum_k A[m][k] * B[n][k]; 128x128 tile, BK=16, 256 threads, 8x8 per thread.
#define GM_BM 128
#define GM_BN 128
#define GM_BK 16
__global__ __launch_bounds__(256, 2) void gemm_in_kernel(const float* __restrict__ spk,
                                                         const float* __restrict__ Win) {
    __shared__ float As[GM_BK][GM_BM];
    __shared__ float Bs[GM_BK][GM_BN];

    const int m0 = blockIdx.y * GM_BM;
    const int n0 = blockIdx.x * GM_BN;
    const int t  = threadIdx.x;
    const int tx = t & 15;          // 0..15 -> n
    const int ty = t >> 4;          // 0..15 -> m
    const int lrow = t >> 2;        // 0..63
    const int lkq  = t & 3;         // k-quad 0..3

    float acc[8][8];
    #pragma unroll
    for (int i = 0; i < 8; i++)
        #pragma unroll
        for (int j = 0; j < 8; j++) acc[i][j] = 0.0f;

    for (int k0 = 0; k0 < IN_DIM; k0 += GM_BK) {
        #pragma unroll
        for (int s = 0; s < 2; s++) {
            int r = lrow + s * 64;
            float4 va = *(const float4*)&spk[(size_t)(m0 + r) * IN_DIM + k0 + lkq * 4];
            As[lkq * 4 + 0][r] = va.x;
            As[lkq * 4 + 1][r] = va.y;
            As[lkq * 4 + 2][r] = va.z;
            As[lkq * 4 + 3][r] = va.w;
            float4 vb = *(const float4*)&Win[(size_t)(n0 + r) * IN_DIM + k0 + lkq * 4];
            Bs[lkq * 4 + 0][r] = vb.x;
            Bs[lkq * 4 + 1][r] = vb.y;
            Bs[lkq * 4 + 2][r] = vb.z;
            Bs[lkq * 4 + 3][r] = vb.w;
        }
        __syncthreads();

        #pragma unroll
        for (int k = 0; k < GM_BK; k++) {
            float a[8], b[8];
            *(float4*)&a[0] = *(float4*)&As[k][ty * 8];
            *(float4*)&a[4] = *(float4*)&As[k][ty * 8 + 4];
            *(float4*)&b[0] = *(float4*)&Bs[k][tx * 8];
            *(float4*)&b[4] = *(float4*)&Bs[k][tx * 8 + 4];
            #pragma unroll
            for (int i = 0; i < 8; i++)
                #pragma unroll
                for (int j = 0; j < 8; j++) acc[i][j] = fmaf(a[i], b[j], acc[i][j]);
        }
        __syncthreads();
    }

    #pragma unroll
    for (int i = 0; i < 8; i++) {
        float* crow = &g_Iin[(size_t)(m0 + ty * 8 + i) * HID + n0 + tx * 8];
        *(float4*)&crow[0] = make_float4(acc[i][0], acc[i][1], acc[i][2], acc[i][3]);
        *(float4*)&crow[4] = make_float4(acc[i][4], acc[i][5], acc[i][6], acc[i][7]);
    }
}

// ---------------- per-step GEMM 1: U[b,p] += sum_h th[b,h] * pout[h,p] ----------------
// Split-K with atomics: grid (h_chunk=16, b_tile=4), tile 64b x 64p over 64 h.
__global__ __launch_bounds__(256) void gemm_U_kernel(const float* __restrict__ pout, int buf) {
    __shared__ float ths[64][68];    // [h][b] transposed, padded
    __shared__ float pouts[64][68];  // [h][p]
    const int h0 = blockIdx.x * 64;
    const int b0 = blockIdx.y * 64;
    const int t  = threadIdx.x;

    #pragma unroll
    for (int s = 0; s < 4; s++) {
        int f   = t + s * 256;     // 0..1023
        int row = f >> 4;          // 0..63
        int c4  = f & 15;
        float4 v = *(const float4*)&g_th[(size_t)(b0 + row) * HID + h0 + c4 * 4];
        ths[c4 * 4 + 0][row] = v.x;
        ths[c4 * 4 + 1][row] = v.y;
        ths[c4 * 4 + 2][row] = v.z;
        ths[c4 * 4 + 3][row] = v.w;
        float4 w = *(const float4*)&pout[(size_t)(h0 + row) * P_DIM + c4 * 4];
        *(float4*)&pouts[row][c4 * 4] = w;
    }
    __syncthreads();

    const int pi = t & 15;   // p quad
    const int bi = t >> 4;   // b quad
    float acc[4][4];
    #pragma unroll
    for (int i = 0; i < 4; i++)
        #pragma unroll
        for (int j = 0; j < 4; j++) acc[i][j] = 0.0f;

    #pragma unroll 4
    for (int h = 0; h < 64; h++) {
        float4 a  = *(float4*)&ths[h][bi * 4];
        float4 bb = *(float4*)&pouts[h][pi * 4];
        float av[4] = {a.x, a.y, a.z, a.w};
        float bv[4] = {bb.x, bb.y, bb.z, bb.w};
        #pragma unroll
        for (int i = 0; i < 4; i++)
            #pragma unroll
            for (int j = 0; j < 4; j++) acc[i][j] = fmaf(av[i], bv[j], acc[i][j]);
    }

    #pragma unroll
    for (int i = 0; i < 4; i++)
        #pragma unroll
        for (int j = 0; j < 4; j++)
            atomicAdd(&g_U[buf][(b0 + bi * 4 + i) * P_DIM + pi * 4 + j], acc[i][j]);
}

// ---------------- per-step GEMM 2 + fused state update ----------------
// rec[b,h] = sum_p U[b,p] * Wpl[h,p];  mem = (Iin + rec - mem)*alpha;
// th = tanh(mem); rm = max(rm, th). Also zeroes the other U buffer.
__global__ __launch_bounds__(256) void step_update_kernel(int t) {
    __shared__ float Us[64][68];  // [p][b]
    __shared__ float Ws[64][68];  // [p][h]
    const int h0  = blockIdx.x * 64;   // gridDim.x = 16
    const int b0  = blockIdx.y * 64;   // gridDim.y = 4
    const int tid = threadIdx.x;
    const int buf = t & 1;

    #pragma unroll
    for (int s = 0; s < 4; s++) {
        int f   = tid + s * 256;
        int row = f >> 4;
        int c4  = f & 15;
        float4 u = *(const float4*)&g_U[buf][(b0 + row) * P_DIM + c4 * 4];
        Us[c4 * 4 + 0][row] = u.x;
        Us[c4 * 4 + 1][row] = u.y;
        Us[c4 * 4 + 2][row] = u.z;
        Us[c4 * 4 + 3][row] = u.w;
        float4 w = *(const float4*)&g_Wpl[(size_t)(h0 + row) * P_DIM + c4 * 4];
        Ws[c4 * 4 + 0][row] = w.x;
        Ws[c4 * 4 + 1][row] = w.y;
        Ws[c4 * 4 + 2][row] = w.z;
        Ws[c4 * 4 + 3][row] = w.w;
    }
    // zero the OTHER buffer for the next step's accumulation (safe: its consumer
    // ran in the previous stream-ordered kernel; its producer runs next step).
    {
        int flat = blockIdx.y * 16 + blockIdx.x;   // 0..63
        ((float*)g_U[buf ^ 1])[flat * 256 + tid] = 0.0f;
    }
    __syncthreads();

    const int hx = tid & 15;   // h quad
    const int by = tid >> 4;   // b quad
    float acc[4][4];
    #pragma unroll
    for (int i = 0; i < 4; i++)
        #pragma unroll
        for (int j = 0; j < 4; j++) acc[i][j] = 0.0f;

    #pragma unroll 4
    for (int p = 0; p < 64; p++) {
        float4 a  = *(float4*)&Us[p][by * 4];
        float4 bb = *(float4*)&Ws[p][hx * 4];
        float av[4] = {a.x, a.y, a.z, a.w};
        float bv[4] = {bb.x, bb.y, bb.z, bb.w};
        #pragma unroll
        for (int i = 0; i < 4; i++)
            #pragma unroll
            for (int j = 0; j < 4; j++) acc[i][j] = fmaf(av[i], bv[j], acc[i][j]);
    }

    const size_t tOff = (size_t)t * BATCH * HID;
    #pragma unroll
    for (int i = 0; i < 4; i++) {
        int b = b0 + by * 4 + i;
        size_t idx = (size_t)b * HID + h0 + hx * 4;
        float4 iin = *(const float4*)&g_Iin[tOff + idx];
        float4 mo  = *(float4*)&g_mem[idx];
        float4 ro  = *(float4*)&g_rm[idx];
        float4 nm, nt;
        nm.x = (iin.x + acc[i][0] - mo.x) * ALPHA;  nt.x = tanhf(nm.x);
        nm.y = (iin.y + acc[i][1] - mo.y) * ALPHA;  nt.y = tanhf(nm.y);
        nm.z = (iin.z + acc[i][2] - mo.z) * ALPHA;  nt.z = tanhf(nm.z);
        nm.w = (iin.w + acc[i][3] - mo.w) * ALPHA;  nt.w = tanhf(nm.w);
        ro.x = fmaxf(ro.x, nt.x);
        ro.y = fmaxf(ro.y, nt.y);
        ro.z = fmaxf(ro.z, nt.z);
        ro.w = fmaxf(ro.w, nt.w);
        *(float4*)&g_mem[idx] = nm;
        *(float4*)&g_th[idx]  = nt;
        *(float4*)&g_rm[idx]  = ro;
    }
}

// ---------------- readout: softmax(rm @ Wout^T), one warp per batch row ----------------
__global__ void readout_kernel(const float* __restrict__ Wout, float* __restrict__ out) {
    const int b    = blockIdx.x;
    const int lane = threadIdx.x;
    float p[OUTD];
    #pragma unroll
    for (int o = 0; o < OUTD; o++) p[o] = 0.0f;

    for (int h = lane; h < HID; h += 32) {
        float r = g_rm[(size_t)b * HID + h];
        #pragma unroll
        for (int o = 0; o < OUTD; o++) p[o] = fmaf(r, Wout[o * HID + h], p[o]);
    }
    #pragma unroll
    for (int o = 0; o < OUTD; o++) {
        #pragma unroll
        for (int off = 16; off > 0; off >>= 1)
            p[o] += __shfl_down_sync(0xffffffffu, p[o], off);
    }
    if (lane == 0) {
        float mx = p[0];
        #pragma unroll
        for (int o = 1; o < OUTD; o++) mx = fmaxf(mx, p[o]);
        float e[OUTD], s = 0.0f;
        #pragma unroll
        for (int o = 0; o < OUTD; o++) { e[o] = expf(p[o] - mx); s += e[o]; }
        float inv = 1.0f / s;
        #pragma unroll
        for (int o = 0; o < OUTD; o++) out[b * OUTD + o] = e[o] * inv;
    }
}

// ---------------- launch ----------------
extern "C" void kernel_launch(void* const* d_in, const int* in_sizes, int n_in,
                              void* d_out, int out_size) {
    const float* spk  = (const float*)d_in[0];  // [100,256,784]
    const float* Win  = (const float*)d_in[1];  // [1024,784]
    const float* Wout = (const float*)d_in[2];  // [10,1024]
    const float* pin  = (const float*)d_in[3];  // [1024,64]
    const float* pout = (const float*)d_in[4];  // [1024,64]
    const float* l    = (const float*)d_in[5];  // [64]
    float* out = (float*)d_out;                 // [256,10]

    prep_kernel<<<1024, 256>>>(pin, l);
    gemm_in_kernel<<<dim3(HID / GM_BN, (T_STEPS * BATCH) / GM_BM), 256>>>(spk, Win);
    for (int t = 0; t < T_STEPS; t++) {
        gemm_U_kernel<<<dim3(16, 4), 256>>>(pout, t & 1);
        step_update_kernel<<<dim3(16, 4), 256>>>(t);
    }
    readout_kernel<<<BATCH, 32>>>(Wout, out);
}

// round 3
// speedup vs baseline: 1.6022x; 1.6022x over previous
#include <cuda_runtime.h>
#include <cooperative_groups.h>
#include <math.h>

namespace cg = cooperative_groups;

#define T_STEPS 100
#define BATCH   256
#define IN_DIM  784
#define HID     1024
#define OUTD    10
#define P_DIM   64
#define ALPHA   0.05f   // DT / TAUM

#define CLUSTER_N   4
#define ROWS_PER_CL 8
#define H_PER_CTA   256           // HID / CLUSTER_N
#define NCTAS       128           // (BATCH/ROWS_PER_CL) * CLUSTER_N

// ---------------- scratch (static device globals) ----------------
__device__ float g_Iin[(size_t)T_STEPS * BATCH * HID];  // [t][b][h]
__device__ float g_rm [BATCH * HID];                    // final running max

// ---------------- big GEMM: Iin = spk @ Win^T  (M=25600, N=1024, K=784) ----------------
#define GM_BM 128
#define GM_BN 128
#define GM_BK 16
__global__ __launch_bounds__(256, 2) void gemm_in_kernel(const float* __restrict__ spk,
                                                         const float* __restrict__ Win) {
    __shared__ float As[GM_BK][GM_BM];
    __shared__ float Bs[GM_BK][GM_BN];

    const int m0 = blockIdx.y * GM_BM;
    const int n0 = blockIdx.x * GM_BN;
    const int t  = threadIdx.x;
    const int tx = t & 15;
    const int ty = t >> 4;
    const int lrow = t >> 2;
    const int lkq  = t & 3;

    float acc[8][8];
    #pragma unroll
    for (int i = 0; i < 8; i++)
        #pragma unroll
        for (int j = 0; j < 8; j++) acc[i][j] = 0.0f;

    for (int k0 = 0; k0 < IN_DIM; k0 += GM_BK) {
        #pragma unroll
        for (int s = 0; s < 2; s++) {
            int r = lrow + s * 64;
            float4 va = *(const float4*)&spk[(size_t)(m0 + r) * IN_DIM + k0 + lkq * 4];
            As[lkq * 4 + 0][r] = va.x;
            As[lkq * 4 + 1][r] = va.y;
            As[lkq * 4 + 2][r] = va.z;
            As[lkq * 4 + 3][r] = va.w;
            float4 vb = *(const float4*)&Win[(size_t)(n0 + r) * IN_DIM + k0 + lkq * 4];
            Bs[lkq * 4 + 0][r] = vb.x;
            Bs[lkq * 4 + 1][r] = vb.y;
            Bs[lkq * 4 + 2][r] = vb.z;
            Bs[lkq * 4 + 3][r] = vb.w;
        }
        __syncthreads();

        #pragma unroll
        for (int k = 0; k < GM_BK; k++) {
            float a[8], b[8];
            *(float4*)&a[0] = *(float4*)&As[k][ty * 8];
            *(float4*)&a[4] = *(float4*)&As[k][ty * 8 + 4];
            *(float4*)&b[0] = *(float4*)&Bs[k][tx * 8];
            *(float4*)&b[4] = *(float4*)&Bs[k][tx * 8 + 4];
            #pragma unroll
            for (int i = 0; i < 8; i++)
                #pragma unroll
                for (int j = 0; j < 8; j++) acc[i][j] = fmaf(a[i], b[j], acc[i][j]);
        }
        __syncthreads();
    }

    #pragma unroll
    for (int i = 0; i < 8; i++) {
        float* crow = &g_Iin[(size_t)(m0 + ty * 8 + i) * HID + n0 + tx * 8];
        *(float4*)&crow[0] = make_float4(acc[i][0], acc[i][1], acc[i][2], acc[i][3]);
        *(float4*)&crow[4] = make_float4(acc[i][4], acc[i][5], acc[i][6], acc[i][7]);
    }
}

// ---------------- persistent clustered scan kernel ----------------
// Cluster of 4 CTAs owns 8 batch rows; CTA rank q owns h in [q*256, q*256+256).
// Per step: U_partial (over own h) -> DSMEM mailbox exchange -> cluster.sync ->
// full U -> rec -> mem/th/rm update. mem & rm live in registers for all 100 steps.
struct LoopSmem {
    float poutT[P_DIM][H_PER_CTA + 4];           // [p][h_local], padded vs bank conflicts
    float Wpl  [H_PER_CTA][P_DIM + 4];           // [h_local][p] = pin*l, padded
    float th   [ROWS_PER_CL][H_PER_CTA];         // tanh(mem) for own h
    float U    [ROWS_PER_CL][P_DIM];             // reduced U
    float mbox [2][CLUSTER_N][ROWS_PER_CL][P_DIM];  // double-buffered partials
};

__global__ void __cluster_dims__(CLUSTER_N, 1, 1) __launch_bounds__(256, 1)
loop_kernel(const float* __restrict__ pin, const float* __restrict__ pout,
            const float* __restrict__ l) {
    extern __shared__ char smraw[];
    LoopSmem* s = (LoopSmem*)smraw;

    cg::cluster_group cl = cg::this_cluster();
    const int rank = cl.block_rank();
    const int cidx = blockIdx.x / CLUSTER_N;
    const int b0   = cidx * ROWS_PER_CL;
    const int H0   = rank * H_PER_CTA;
    const int tid  = threadIdx.x;

    // ---- load weights into SMEM (pout transposed; Wpl = pin * l) ----
    for (int i = tid; i < H_PER_CTA * (P_DIM / 4); i += 256) {
        int hl = i >> 4;            // 0..255
        int p4 = i & 15;            // 0..15
        float4 v  = *(const float4*)&pout[(size_t)(H0 + hl) * P_DIM + p4 * 4];
        s->poutT[p4 * 4 + 0][hl] = v.x;
        s->poutT[p4 * 4 + 1][hl] = v.y;
        s->poutT[p4 * 4 + 2][hl] = v.z;
        s->poutT[p4 * 4 + 3][hl] = v.w;
        float4 w  = *(const float4*)&pin[(size_t)(H0 + hl) * P_DIM + p4 * 4];
        float4 lv = *(const float4*)&l[p4 * 4];
        s->Wpl[hl][p4 * 4 + 0] = w.x * lv.x;
        s->Wpl[hl][p4 * 4 + 1] = w.y * lv.y;
        s->Wpl[hl][p4 * 4 + 2] = w.z * lv.z;
        s->Wpl[hl][p4 * 4 + 3] = w.w * lv.w;
    }
    for (int i = tid; i < ROWS_PER_CL * H_PER_CTA; i += 256)
        ((float*)s->th)[i] = 0.0f;

    // ---- persistent per-thread state ----
    const int p  = tid & 63;        // p index (phase A) == h0 (phase B)
    const int g  = tid >> 6;        // row group 0..3
    const int r0 = 2 * g, r1 = 2 * g + 1;

    float memv[2][4], rmv[2][4];
    #pragma unroll
    for (int r = 0; r < 2; r++)
        #pragma unroll
        for (int hi = 0; hi < 4; hi++) { memv[r][hi] = 0.0f; rmv[r][hi] = -2.0f; }

    // precompute peer mailbox row pointers (slot = my rank, rows r0/r1)
    float* mb0[CLUSTER_N];
    float* mb1[CLUSTER_N];
    #pragma unroll
    for (int rk = 0; rk < CLUSTER_N; rk++) {
        LoopSmem* ps = (LoopSmem*)cl.map_shared_rank((void*)s, rk);
        mb0[rk] = &ps->mbox[0][rank][0][0];
        mb1[rk] = &ps->mbox[1][rank][0][0];
    }

    cl.sync();   // everyone's SMEM initialized before first exchange

    for (int t = 0; t < T_STEPS; t++) {
        __syncthreads();             // th(t-1) writes visible to phase A
        const int buf = t & 1;

        // prefetch Iin[t] for my 8 outputs (coalesced)
        float iin[2][4];
        {
            const size_t bA = ((size_t)t * BATCH + b0 + r0) * HID + H0 + p;
            const size_t bB = ((size_t)t * BATCH + b0 + r1) * HID + H0 + p;
            #pragma unroll
            for (int hi = 0; hi < 4; hi++) {
                iin[0][hi] = __ldcs(&g_Iin[bA + hi * 64]);
                iin[1][hi] = __ldcs(&g_Iin[bB + hi * 64]);
            }
        }

        // ---- phase A: partial U[r][p] over own h ----
        float a0 = 0.0f, a1 = 0.0f;
        const float4* wp = (const float4*)&s->poutT[p][0];
        const float4* t0p = (const float4*)&s->th[r0][0];
        const float4* t1p = (const float4*)&s->th[r1][0];
        #pragma unroll 8
        for (int h4 = 0; h4 < H_PER_CTA / 4; h4++) {
            float4 w  = wp[h4];
            float4 t0 = t0p[h4];
            float4 t1 = t1p[h4];
            a0 = fmaf(w.x, t0.x, a0); a0 = fmaf(w.y, t0.y, a0);
            a0 = fmaf(w.z, t0.z, a0); a0 = fmaf(w.w, t0.w, a0);
            a1 = fmaf(w.x, t1.x, a1); a1 = fmaf(w.y, t1.y, a1);
            a1 = fmaf(w.z, t1.z, a1); a1 = fmaf(w.w, t1.w, a1);
        }
        // scatter partials to all 4 cluster CTAs: mbox[buf][myrank][row][p]
        #pragma unroll
        for (int rk = 0; rk < CLUSTER_N; rk++) {
            float* base = buf ? mb1[rk] : mb0[rk];
            base[r0 * P_DIM + p] = a0;
            base[r1 * P_DIM + p] = a1;
        }

        cl.sync();   // partials visible cluster-wide

        // ---- reduce 4 partials -> s->U[row][p] ----
        #pragma unroll
        for (int kk = 0; kk < 2; kk++) {
            int k2 = tid + kk * 256;
            int pp = k2 & 63, rr = k2 >> 6;
            s->U[rr][pp] = s->mbox[buf][0][rr][pp] + s->mbox[buf][1][rr][pp]
                         + s->mbox[buf][2][rr][pp] + s->mbox[buf][3][rr][pp];
        }
        __syncthreads();

        // ---- phase B: rec[r][h] = U[r][:] . Wpl[h][:], then state update ----
        const float4* u0p = (const float4*)&s->U[r0][0];
        const float4* u1p = (const float4*)&s->U[r1][0];
        #pragma unroll
        for (int hi = 0; hi < 4; hi++) {
            const int h = p + hi * 64;
            const float4* wl = (const float4*)&s->Wpl[h][0];
            float c0 = 0.0f, c1 = 0.0f;
            #pragma unroll
            for (int p4 = 0; p4 < P_DIM / 4; p4++) {
                float4 w  = wl[p4];
                float4 u0 = u0p[p4];
                float4 u1 = u1p[p4];
                c0 = fmaf(w.x, u0.x, c0); c0 = fmaf(w.y, u0.y, c0);
                c0 = fmaf(w.z, u0.z, c0); c0 = fmaf(w.w, u0.w, c0);
                c1 = fmaf(w.x, u1.x, c1); c1 = fmaf(w.y, u1.y, c1);
                c1 = fmaf(w.z, u1.z, c1); c1 = fmaf(w.w, u1.w, c1);
            }
            float m0 = (iin[0][hi] + c0 - memv[0][hi]) * ALPHA;
            float m1 = (iin[1][hi] + c1 - memv[1][hi]) * ALPHA;
            memv[0][hi] = m0;  memv[1][hi] = m1;
            float tv0 = tanhf(m0), tv1 = tanhf(m1);
            rmv[0][hi] = fmaxf(rmv[0][hi], tv0);
            rmv[1][hi] = fmaxf(rmv[1][hi], tv1);
            s->th[r0][h] = tv0;
            s->th[r1][h] = tv1;
        }
    }

    // ---- write running max to global for readout ----
    #pragma unroll
    for (int hi = 0; hi < 4; hi++) {
        g_rm[(size_t)(b0 + r0) * HID + H0 + p + hi * 64] = rmv[0][hi];
        g_rm[(size_t)(b0 + r1) * HID + H0 + p + hi * 64] = rmv[1][hi];
    }
}

// ---------------- readout: softmax(rm @ Wout^T), one warp per batch row ----------------
__global__ void readout_kernel(const float* __restrict__ Wout, float* __restrict__ out) {
    const int b    = blockIdx.x;
    const int lane = threadIdx.x;
    float pacc[OUTD];
    #pragma unroll
    for (int o = 0; o < OUTD; o++) pacc[o] = 0.0f;

    for (int h = lane; h < HID; h += 32) {
        float r = g_rm[(size_t)b * HID + h];
        #pragma unroll
        for (int o = 0; o < OUTD; o++) pacc[o] = fmaf(r, Wout[o * HID + h], pacc[o]);
    }
    #pragma unroll
    for (int o = 0; o < OUTD; o++) {
        #pragma unroll
        for (int off = 16; off > 0; off >>= 1)
            pacc[o] += __shfl_down_sync(0xffffffffu, pacc[o], off);
    }
    if (lane == 0) {
        float mx = pacc[0];
        #pragma unroll
        for (int o = 1; o < OUTD; o++) mx = fmaxf(mx, pacc[o]);
        float e[OUTD], sum = 0.0f;
        #pragma unroll
        for (int o = 0; o < OUTD; o++) { e[o] = expf(pacc[o] - mx); sum += e[o]; }
        float inv = 1.0f / sum;
        #pragma unroll
        for (int o = 0; o < OUTD; o++) out[b * OUTD + o] = e[o] * inv;
    }
}

// ---------------- launch ----------------
extern "C" void kernel_launch(void* const* d_in, const int* in_sizes, int n_in,
                              void* d_out, int out_size) {
    const float* spk  = (const float*)d_in[0];  // [100,256,784]
    const float* Win  = (const float*)d_in[1];  // [1024,784]
    const float* Wout = (const float*)d_in[2];  // [10,1024]
    const float* pin  = (const float*)d_in[3];  // [1024,64]
    const float* pout = (const float*)d_in[4];  // [1024,64]
    const float* l    = (const float*)d_in[5];  // [64]
    float* out = (float*)d_out;                 // [256,10]

    static bool attr_set = false;
    if (!attr_set) {
        cudaFuncSetAttribute(loop_kernel, cudaFuncAttributeMaxDynamicSharedMemorySize,
                             (int)sizeof(LoopSmem));
        attr_set = true;
    }

    gemm_in_kernel<<<dim3(HID / GM_BN, (T_STEPS * BATCH) / GM_BM), 256>>>(spk, Win);
    loop_kernel<<<NCTAS, 256, sizeof(LoopSmem)>>>(pin, pout, l);
    readout_kernel<<<BATCH, 32>>>(Wout, out);
}

// round 5
// speedup vs baseline: 3.2875x; 2.0519x over previous
#include <cuda_runtime.h>
#include <cuda_bf16.h>
#include <cooperative_groups.h>
#include <math.h>
#include <stdint.h>

namespace cg = cooperative_groups;

#define T_STEPS 100
#define BATCH   256
#define IN_DIM  784
#define HID     1024
#define OUTD    10
#define P_DIM   64
#define ALPHA   0.05f   // DT / TAUM

#define M_TOT   (T_STEPS * BATCH)   // 25600
#define K_PAD   832                 // 13 * 64
#define N_CHUNK 13

// ---------------- scratch (static device globals) ----------------
__device__ float g_Iin[(size_t)T_STEPS * BATCH * HID];   // [t*b][h]
__device__ float g_rm [BATCH * HID];
__device__ __nv_bfloat16 g_spkb [(size_t)M_TOT * K_PAD]; // bf16 spikes, K-padded
__device__ __nv_bfloat16 g_WinHi[(size_t)HID * K_PAD];
__device__ __nv_bfloat16 g_WinLo[(size_t)HID * K_PAD];

// ---------------- helpers ----------------
__device__ __forceinline__ uint32_t smem_u32(const void* p) {
    uint32_t a;
    asm("{ .reg .u64 t; cvta.to.shared.u64 t, %1; cvt.u32.u64 %0, t; }" : "=r"(a) : "l"(p));
    return a;
}
#define SWZ128(o) ((o) ^ (((o) >> 3) & 0x70))
#define CP_COMMIT() asm volatile("cp.async.commit_group;" ::: "memory")
#define CP_WAIT(n)  asm volatile("cp.async.wait_group %0;" :: "n"(n) : "memory")

__device__ __forceinline__ void ldm_x4(uint32_t* r, uint32_t addr) {
    asm volatile("ldmatrix.sync.aligned.m8n8.x4.shared.b16 {%0,%1,%2,%3}, [%4];"
                 : "=r"(r[0]), "=r"(r[1]), "=r"(r[2]), "=r"(r[3]) : "r"(addr));
}
__device__ __forceinline__ void mma_bf16(float* c, const uint32_t* a, uint32_t b0, uint32_t b1) {
    asm volatile("mma.sync.aligned.m16n8k16.row.col.f32.bf16.bf16.f32 "
                 "{%0,%1,%2,%3}, {%4,%5,%6,%7}, {%8,%9}, {%0,%1,%2,%3};"
                 : "+f"(c[0]), "+f"(c[1]), "+f"(c[2]), "+f"(c[3])
                 : "r"(a[0]), "r"(a[1]), "r"(a[2]), "r"(a[3]), "r"(b0), "r"(b1));
}

// ---------------- prep: bf16 conversion + K-padding ----------------
__global__ void prep_spk_kernel(const float* __restrict__ spk) {
    int i = blockIdx.x * blockDim.x + threadIdx.x;
    if (i >= M_TOT * (K_PAD / 8)) return;
    int row = i / (K_PAD / 8);
    int c0  = (i % (K_PAD / 8)) * 8;
    __nv_bfloat16 v[8];
    #pragma unroll
    for (int j = 0; j < 8; j++) {
        int c = c0 + j;
        float f = (c < IN_DIM) ? spk[(size_t)row * IN_DIM + c] : 0.0f;
        v[j] = __float2bfloat16(f);
    }
    *(uint4*)&g_spkb[(size_t)row * K_PAD + c0] = *(uint4*)v;
}

__global__ void prep_win_kernel(const float* __restrict__ Win) {
    int i = blockIdx.x * blockDim.x + threadIdx.x;
    if (i >= HID * (K_PAD / 8)) return;
    int row = i / (K_PAD / 8);
    int c0  = (i % (K_PAD / 8)) * 8;
    __nv_bfloat16 hi[8], lo[8];
    #pragma unroll
    for (int j = 0; j < 8; j++) {
        int c = c0 + j;
        float f = (c < IN_DIM) ? Win[(size_t)row * IN_DIM + c] : 0.0f;
        __nv_bfloat16 h = __float2bfloat16(f);
        hi[j] = h;
        lo[j] = __float2bfloat16(f - __bfloat162float(h));
    }
    *(uint4*)&g_WinHi[(size_t)row * K_PAD + c0] = *(uint4*)hi;
    *(uint4*)&g_WinLo[(size_t)row * K_PAD + c0] = *(uint4*)lo;
}

// ---------------- HMMA GEMM: Iin = spkb @ (WinHi+WinLo)^T ----------------
// 128M x 128N per CTA; K chunks of 64 bf16 (128B SW128 rows); 2-stage cp.async.
// 8 warps: warp grid 4(m) x 2(n), warp tile 32m x 64n, fp32 accumulators.
#define TILE_BYTES  16384                       // 128 rows * 128 B
#define STAGE_BYTES (3 * TILE_BYTES)            // A, Bhi, Blo
#define SM_TOTAL    (2 * STAGE_BYTES)           // 98304

__device__ __forceinline__ void copy_tile(uint32_t sdst, const __nv_bfloat16* __restrict__ g,
                                          int row0, int k0, int tid) {
    #pragma unroll
    for (int j = 0; j < 4; j++) {
        int i   = tid + j * 256;      // 0..1023
        int row = i >> 3;
        int cb  = i & 7;              // 16B block within 128B row
        const void* gp = g + (size_t)(row0 + row) * K_PAD + k0 + cb * 8;
        uint32_t so = sdst + SWZ128(row * 128 + cb * 16);
        asm volatile("cp.async.cg.shared.global [%0], [%1], 16;" :: "r"(so), "l"(gp));
    }
}

__global__ __launch_bounds__(256, 2) void gemm_mma_kernel() {
    extern __shared__ char smraw[];
    const uint32_t sb  = smem_u32(smraw);
    const int tid  = threadIdx.x;
    const int wid  = tid >> 5;
    const int lane = tid & 31;
    const int m0 = blockIdx.y * 128;
    const int n0 = blockIdx.x * 128;
    const int wm = (wid & 3) * 32;     // warp m offset in tile
    const int wn = (wid >> 2) * 64;    // warp n offset in tile

    const uint32_t stA[2]  = {sb,                       sb + STAGE_BYTES};
    const uint32_t stBh[2] = {stA[0] + TILE_BYTES,      stA[1] + TILE_BYTES};
    const uint32_t stBl[2] = {stBh[0] + TILE_BYTES,     stBh[1] + TILE_BYTES};

    float acc[2][8][4];
    #pragma unroll
    for (int mi = 0; mi < 2; mi++)
        #pragma unroll
        for (int nj = 0; nj < 8; nj++)
            #pragma unroll
            for (int q = 0; q < 4; q++) acc[mi][nj][q] = 0.0f;

    // prologue: chunks 0,1
    copy_tile(stA[0], g_spkb, m0, 0, tid);
    copy_tile(stBh[0], g_WinHi, n0, 0, tid);
    copy_tile(stBl[0], g_WinLo, n0, 0, tid);
    CP_COMMIT();
    copy_tile(stA[1], g_spkb, m0, 64, tid);
    copy_tile(stBh[1], g_WinHi, n0, 64, tid);
    copy_tile(stBl[1], g_WinLo, n0, 64, tid);
    CP_COMMIT();

    // per-lane ldmatrix address components (within a 128x64 bf16 tile, SW128)
    const int arow = wm + (lane & 15);                       // A rows 0-15 of frag pair
    const int acolL = (lane >> 4) << 4;                      // 0 or 16 bytes (k0/k8)
    const int brow = (lane & 7) + ((lane >> 4) << 3);        // B n row within n16 block
    const int bcolL = ((lane >> 3) & 1) << 4;                // 0 or 16 bytes

    for (int k = 0; k < N_CHUNK; k++) {
        const int s = k & 1;
        if (k < N_CHUNK - 1) CP_WAIT(1); else CP_WAIT(0);
        __syncthreads();

        #pragma unroll
        for (int ks = 0; ks < 4; ks++) {
            const int kb = ks * 32;    // byte offset of this k16 within the 128B row
            uint32_t af[2][4];
            ldm_x4(af[0], stA[s] + SWZ128((arow)      * 128 + kb + acolL));
            ldm_x4(af[1], stA[s] + SWZ128((arow + 16) * 128 + kb + acolL));

            #pragma unroll
            for (int nb = 0; nb < 4; nb++) {
                const uint32_t boff = SWZ128((wn + nb * 16 + brow) * 128 + kb + bcolL);
                uint32_t bh[4], bl[4];
                ldm_x4(bh, stBh[s] + boff);
                ldm_x4(bl, stBl[s] + boff);
                #pragma unroll
                for (int mi = 0; mi < 2; mi++) {
                    mma_bf16(acc[mi][nb * 2 + 0], af[mi], bh[0], bh[1]);
                    mma_bf16(acc[mi][nb * 2 + 1], af[mi], bh[2], bh[3]);
                    mma_bf16(acc[mi][nb * 2 + 0], af[mi], bl[0], bl[1]);
                    mma_bf16(acc[mi][nb * 2 + 1], af[mi], bl[2], bl[3]);
                }
            }
        }
        __syncthreads();

        if (k + 2 < N_CHUNK) {
            const int k0 = (k + 2) * 64;
            copy_tile(stA[s], g_spkb, m0, k0, tid);
            copy_tile(stBh[s], g_WinHi, n0, k0, tid);
            copy_tile(stBl[s], g_WinLo, n0, k0, tid);
            CP_COMMIT();
        }
    }

    // epilogue: write accumulators to g_Iin
    const int r0 = lane >> 2;          // 0..7
    const int c0 = (lane & 3) * 2;     // 0,2,4,6
    #pragma unroll
    for (int mi = 0; mi < 2; mi++) {
        #pragma unroll
        for (int nj = 0; nj < 8; nj++) {
            const int row = m0 + wm + mi * 16 + r0;
            const int col = n0 + wn + nj * 8 + c0;
            float* base = &g_Iin[(size_t)row * HID + col];
            *(float2*)base                    = make_float2(acc[mi][nj][0], acc[mi][nj][1]);
            *(float2*)(base + 8 * HID)        = make_float2(acc[mi][nj][2], acc[mi][nj][3]);
        }
    }
}

// ---------------- persistent clustered scan kernel (unchanged from R3) ----------------
#define CLUSTER_N   4
#define ROWS_PER_CL 8
#define H_PER_CTA   256
#define NCTAS       128

struct LoopSmem {
    float poutT[P_DIM][H_PER_CTA + 4];
    float Wpl  [H_PER_CTA][P_DIM + 4];
    float th   [ROWS_PER_CL][H_PER_CTA];
    float U    [ROWS_PER_CL][P_DIM];
    float mbox [2][CLUSTER_N][ROWS_PER_CL][P_DIM];
};

__global__ void __cluster_dims__(CLUSTER_N, 1, 1) __launch_bounds__(256, 1)
loop_kernel(const float* __restrict__ pin, const float* __restrict__ pout,
            const float* __restrict__ l) {
    extern __shared__ char smraw[];
    LoopSmem* s = (LoopSmem*)smraw;

    cg::cluster_group cl = cg::this_cluster();
    const int rank = cl.block_rank();
    const int cidx = blockIdx.x / CLUSTER_N;
    const int b0   = cidx * ROWS_PER_CL;
    const int H0   = rank * H_PER_CTA;
    const int tid  = threadIdx.x;

    for (int i = tid; i < H_PER_CTA * (P_DIM / 4); i += 256) {
        int hl = i >> 4;
        int p4 = i & 15;
        float4 v  = *(const float4*)&pout[(size_t)(H0 + hl) * P_DIM + p4 * 4];
        s->poutT[p4 * 4 + 0][hl] = v.x;
        s->poutT[p4 * 4 + 1][hl] = v.y;
        s->poutT[p4 * 4 + 2][hl] = v.z;
        s->poutT[p4 * 4 + 3][hl] = v.w;
        float4 w  = *(const float4*)&pin[(size_t)(H0 + hl) * P_DIM + p4 * 4];
        float4 lv = *(const float4*)&l[p4 * 4];
        s->Wpl[hl][p4 * 4 + 0] = w.x * lv.x;
        s->Wpl[hl][p4 * 4 + 1] = w.y * lv.y;
        s->Wpl[hl][p4 * 4 + 2] = w.z * lv.z;
        s->Wpl[hl][p4 * 4 + 3] = w.w * lv.w;
    }
    for (int i = tid; i < ROWS_PER_CL * H_PER_CTA; i += 256)
        ((float*)s->th)[i] = 0.0f;

    const int p  = tid & 63;
    const int g  = tid >> 6;
    const int r0 = 2 * g, r1 = 2 * g + 1;

    float memv[2][4], rmv[2][4];
    #pragma unroll
    for (int r = 0; r < 2; r++)
        #pragma unroll
        for (int hi = 0; hi < 4; hi++) { memv[r][hi] = 0.0f; rmv[r][hi] = -2.0f; }

    float* mb0[CLUSTER_N];
    float* mb1[CLUSTER_N];
    #pragma unroll
    for (int rk = 0; rk < CLUSTER_N; rk++) {
        LoopSmem* ps = (LoopSmem*)cl.map_shared_rank((void*)s, rk);
        mb0[rk] = &ps->mbox[0][rank][0][0];
        mb1[rk] = &ps->mbox[1][rank][0][0];
    }

    cl.sync();

    for (int t = 0; t < T_STEPS; t++) {
        __syncthreads();
        const int buf = t & 1;

        float iin[2][4];
        {
            const size_t bA = ((size_t)t * BATCH + b0 + r0) * HID + H0 + p;
            const size_t bB = ((size_t)t * BATCH + b0 + r1) * HID + H0 + p;
            #pragma unroll
            for (int hi = 0; hi < 4; hi++) {
                iin[0][hi] = __ldcs(&g_Iin[bA + hi * 64]);
                iin[1][hi] = __ldcs(&g_Iin[bB + hi * 64]);
            }
        }

        float a0 = 0.0f, a1 = 0.0f;
        const float4* wp  = (const float4*)&s->poutT[p][0];
        const float4* t0p = (const float4*)&s->th[r0][0];
        const float4* t1p = (const float4*)&s->th[r1][0];
        #pragma unroll 8
        for (int h4 = 0; h4 < H_PER_CTA / 4; h4++) {
            float4 w  = wp[h4];
            float4 t0 = t0p[h4];
            float4 t1 = t1p[h4];
            a0 = fmaf(w.x, t0.x, a0); a0 = fmaf(w.y, t0.y, a0);
            a0 = fmaf(w.z, t0.z, a0); a0 = fmaf(w.w, t0.w, a0);
            a1 = fmaf(w.x, t1.x, a1); a1 = fmaf(w.y, t1.y, a1);
            a1 = fmaf(w.z, t1.z, a1); a1 = fmaf(w.w, t1.w, a1);
        }
        #pragma unroll
        for (int rk = 0; rk < CLUSTER_N; rk++) {
            float* base = buf ? mb1[rk] : mb0[rk];
            base[r0 * P_DIM + p] = a0;
            base[r1 * P_DIM + p] = a1;
        }

        cl.sync();

        #pragma unroll
        for (int kk = 0; kk < 2; kk++) {
            int k2 = tid + kk * 256;
            int pp = k2 & 63, rr = k2 >> 6;
            s->U[rr][pp] = s->mbox[buf][0][rr][pp] + s->mbox[buf][1][rr][pp]
                         + s->mbox[buf][2][rr][pp] + s->mbox[buf][3][rr][pp];
        }
        __syncthreads();

        const float4* u0p = (const float4*)&s->U[r0][0];
        const float4* u1p = (const float4*)&s->U[r1][0];
        #pragma unroll
        for (int hi = 0; hi < 4; hi++) {
            const int h = p + hi * 64;
            const float4* wl = (const float4*)&s->Wpl[h][0];
            float c0 = 0.0f, c1 = 0.0f;
            #pragma unroll
            for (int p4 = 0; p4 < P_DIM / 4; p4++) {
                float4 w  = wl[p4];
                float4 u0 = u0p[p4];
                float4 u1 = u1p[p4];
                c0 = fmaf(w.x, u0.x, c0); c0 = fmaf(w.y, u0.y, c0);
                c0 = fmaf(w.z, u0.z, c0); c0 = fmaf(w.w, u0.w, c0);
                c1 = fmaf(w.x, u1.x, c1); c1 = fmaf(w.y, u1.y, c1);
                c1 = fmaf(w.z, u1.z, c1); c1 = fmaf(w.w, u1.w, c1);
            }
            float m0 = (iin[0][hi] + c0 - memv[0][hi]) * ALPHA;
            float m1 = (iin[1][hi] + c1 - memv[1][hi]) * ALPHA;
            memv[0][hi] = m0;  memv[1][hi] = m1;
            float tv0 = tanhf(m0), tv1 = tanhf(m1);
            rmv[0][hi] = fmaxf(rmv[0][hi], tv0);
            rmv[1][hi] = fmaxf(rmv[1][hi], tv1);
            s->th[r0][h] = tv0;
            s->th[r1][h] = tv1;
        }
    }

    #pragma unroll
    for (int hi = 0; hi < 4; hi++) {
        g_rm[(size_t)(b0 + r0) * HID + H0 + p + hi * 64] = rmv[0][hi];
        g_rm[(size_t)(b0 + r1) * HID + H0 + p + hi * 64] = rmv[1][hi];
    }
}

// ---------------- readout ----------------
__global__ void readout_kernel(const float* __restrict__ Wout, float* __restrict__ out) {
    const int b    = blockIdx.x;
    const int lane = threadIdx.x;
    float pacc[OUTD];
    #pragma unroll
    for (int o = 0; o < OUTD; o++) pacc[o] = 0.0f;

    for (int h = lane; h < HID; h += 32) {
        float r = g_rm[(size_t)b * HID + h];
        #pragma unroll
        for (int o = 0; o < OUTD; o++) pacc[o] = fmaf(r, Wout[o * HID + h], pacc[o]);
    }
    #pragma unroll
    for (int o = 0; o < OUTD; o++) {
        #pragma unroll
        for (int off = 16; off > 0; off >>= 1)
            pacc[o] += __shfl_down_sync(0xffffffffu, pacc[o], off);
    }
    if (lane == 0) {
        float mx = pacc[0];
        #pragma unroll
        for (int o = 1; o < OUTD; o++) mx = fmaxf(mx, pacc[o]);
        float e[OUTD], sum = 0.0f;
        #pragma unroll
        for (int o = 0; o < OUTD; o++) { e[o] = expf(pacc[o] - mx); sum += e[o]; }
        float inv = 1.0f / sum;
        #pragma unroll
        for (int o = 0; o < OUTD; o++) out[b * OUTD + o] = e[o] * inv;
    }
}

// ---------------- launch ----------------
extern "C" void kernel_launch(void* const* d_in, const int* in_sizes, int n_in,
                              void* d_out, int out_size) {
    const float* spk  = (const float*)d_in[0];
    const float* Win  = (const float*)d_in[1];
    const float* Wout = (const float*)d_in[2];
    const float* pin  = (const float*)d_in[3];
    const float* pout = (const float*)d_in[4];
    const float* l    = (const float*)d_in[5];
    float* out = (float*)d_out;

    cudaFuncSetAttribute(gemm_mma_kernel, cudaFuncAttributeMaxDynamicSharedMemorySize, SM_TOTAL);
    cudaFuncSetAttribute(loop_kernel, cudaFuncAttributeMaxDynamicSharedMemorySize,
                         (int)sizeof(LoopSmem));

    {
        int n = M_TOT * (K_PAD / 8);
        prep_spk_kernel<<<(n + 255) / 256, 256>>>(spk);
    }
    {
        int n = HID * (K_PAD / 8);
        prep_win_kernel<<<(n + 255) / 256, 256>>>(Win);
    }
    gemm_mma_kernel<<<dim3(HID / 128, M_TOT / 128), 256, SM_TOTAL>>>();
    loop_kernel<<<NCTAS, 256, sizeof(LoopSmem)>>>(pin, pout, l);
    readout_kernel<<<BATCH, 32>>>(Wout, out);
}

// round 6
// speedup vs baseline: 5.2922x; 1.6098x over previous
#include <cuda_runtime.h>
#include <cuda_bf16.h>
#include <cooperative_groups.h>
#include <math.h>
#include <stdint.h>

namespace cg = cooperative_groups;

#define T_STEPS 100
#define BATCH   256
#define IN_DIM  784
#define HID     1024
#define OUTD    10
#define P_DIM   64
#define ALPHA   0.05f   // DT / TAUM

#define M_TOT   (T_STEPS * BATCH)   // 25600
#define K_PAD   832                 // 13 * 64
#define N_CHUNK 13

// ---------------- scratch (static device globals) ----------------
__device__ float g_Iin[(size_t)T_STEPS * BATCH * HID];   // [t*b][h]
__device__ float g_rm [BATCH * HID];
__device__ __nv_bfloat16 g_spkb [(size_t)M_TOT * K_PAD]; // bf16 spikes, K-padded
__device__ __nv_bfloat16 g_WinHi[(size_t)HID * K_PAD];
__device__ __nv_bfloat16 g_WinLo[(size_t)HID * K_PAD];

// ---------------- helpers ----------------
__device__ __forceinline__ uint32_t smem_u32(const void* p) {
    uint32_t a;
    asm("{ .reg .u64 t; cvta.to.shared.u64 t, %1; cvt.u32.u64 %0, t; }" : "=r"(a) : "l"(p));
    return a;
}
#define SWZ128(o) ((o) ^ (((o) >> 3) & 0x70))
#define CP_COMMIT() asm volatile("cp.async.commit_group;" ::: "memory")
#define CP_WAIT(n)  asm volatile("cp.async.wait_group %0;" :: "n"(n) : "memory")

__device__ __forceinline__ void ldm_x4(uint32_t* r, uint32_t addr) {
    asm volatile("ldmatrix.sync.aligned.m8n8.x4.shared.b16 {%0,%1,%2,%3}, [%4];"
                 : "=r"(r[0]), "=r"(r[1]), "=r"(r[2]), "=r"(r[3]) : "r"(addr));
}
__device__ __forceinline__ void mma_bf16(float* c, const uint32_t* a, uint32_t b0, uint32_t b1) {
    asm volatile("mma.sync.aligned.m16n8k16.row.col.f32.bf16.bf16.f32 "
                 "{%0,%1,%2,%3}, {%4,%5,%6,%7}, {%8,%9}, {%0,%1,%2,%3};"
                 : "+f"(c[0]), "+f"(c[1]), "+f"(c[2]), "+f"(c[3])
                 : "r"(a[0]), "r"(a[1]), "r"(a[2]), "r"(a[3]), "r"(b0), "r"(b1));
}

// ---------------- prep: bf16 conversion + K-padding ----------------
__global__ void prep_spk_kernel(const float* __restrict__ spk) {
    int i = blockIdx.x * blockDim.x + threadIdx.x;
    if (i >= M_TOT * (K_PAD / 8)) return;
    int row = i / (K_PAD / 8);
    int c0  = (i % (K_PAD / 8)) * 8;
    __nv_bfloat16 v[8];
    #pragma unroll
    for (int j = 0; j < 8; j++) {
        int c = c0 + j;
        float f = (c < IN_DIM) ? spk[(size_t)row * IN_DIM + c] : 0.0f;
        v[j] = __float2bfloat16(f);
    }
    *(uint4*)&g_spkb[(size_t)row * K_PAD + c0] = *(uint4*)v;
}

__global__ void prep_win_kernel(const float* __restrict__ Win) {
    int i = blockIdx.x * blockDim.x + threadIdx.x;
    if (i >= HID * (K_PAD / 8)) return;
    int row = i / (K_PAD / 8);
    int c0  = (i % (K_PAD / 8)) * 8;
    __nv_bfloat16 hi[8], lo[8];
    #pragma unroll
    for (int j = 0; j < 8; j++) {
        int c = c0 + j;
        float f = (c < IN_DIM) ? Win[(size_t)row * IN_DIM + c] : 0.0f;
        __nv_bfloat16 h = __float2bfloat16(f);
        hi[j] = h;
        lo[j] = __float2bfloat16(f - __bfloat162float(h));
    }
    *(uint4*)&g_WinHi[(size_t)row * K_PAD + c0] = *(uint4*)hi;
    *(uint4*)&g_WinLo[(size_t)row * K_PAD + c0] = *(uint4*)lo;
}

// ---------------- HMMA GEMM: Iin = spkb @ (WinHi+WinLo)^T (unchanged, verified) ----------------
#define TILE_BYTES  16384
#define STAGE_BYTES (3 * TILE_BYTES)
#define SM_TOTAL    (2 * STAGE_BYTES)

__device__ __forceinline__ void copy_tile(uint32_t sdst, const __nv_bfloat16* __restrict__ g,
                                          int row0, int k0, int tid) {
    #pragma unroll
    for (int j = 0; j < 4; j++) {
        int i   = tid + j * 256;
        int row = i >> 3;
        int cb  = i & 7;
        const void* gp = g + (size_t)(row0 + row) * K_PAD + k0 + cb * 8;
        uint32_t so = sdst + SWZ128(row * 128 + cb * 16);
        asm volatile("cp.async.cg.shared.global [%0], [%1], 16;" :: "r"(so), "l"(gp));
    }
}

__global__ __launch_bounds__(256, 2) void gemm_mma_kernel() {
    extern __shared__ char smraw[];
    const uint32_t sb  = smem_u32(smraw);
    const int tid  = threadIdx.x;
    const int wid  = tid >> 5;
    const int lane = tid & 31;
    const int m0 = blockIdx.y * 128;
    const int n0 = blockIdx.x * 128;
    const int wm = (wid & 3) * 32;
    const int wn = (wid >> 2) * 64;

    const uint32_t stA[2]  = {sb,                       sb + STAGE_BYTES};
    const uint32_t stBh[2] = {stA[0] + TILE_BYTES,      stA[1] + TILE_BYTES};
    const uint32_t stBl[2] = {stBh[0] + TILE_BYTES,     stBh[1] + TILE_BYTES};

    float acc[2][8][4];
    #pragma unroll
    for (int mi = 0; mi < 2; mi++)
        #pragma unroll
        for (int nj = 0; nj < 8; nj++)
            #pragma unroll
            for (int q = 0; q < 4; q++) acc[mi][nj][q] = 0.0f;

    copy_tile(stA[0], g_spkb, m0, 0, tid);
    copy_tile(stBh[0], g_WinHi, n0, 0, tid);
    copy_tile(stBl[0], g_WinLo, n0, 0, tid);
    CP_COMMIT();
    copy_tile(stA[1], g_spkb, m0, 64, tid);
    copy_tile(stBh[1], g_WinHi, n0, 64, tid);
    copy_tile(stBl[1], g_WinLo, n0, 64, tid);
    CP_COMMIT();

    const int arow = wm + (lane & 15);
    const int acolL = (lane >> 4) << 4;
    const int brow = (lane & 7) + ((lane >> 4) << 3);
    const int bcolL = ((lane >> 3) & 1) << 4;

    for (int k = 0; k < N_CHUNK; k++) {
        const int s = k & 1;
        if (k < N_CHUNK - 1) CP_WAIT(1); else CP_WAIT(0);
        __syncthreads();

        #pragma unroll
        for (int ks = 0; ks < 4; ks++) {
            const int kb = ks * 32;
            uint32_t af[2][4];
            ldm_x4(af[0], stA[s] + SWZ128((arow)      * 128 + kb + acolL));
            ldm_x4(af[1], stA[s] + SWZ128((arow + 16) * 128 + kb + acolL));

            #pragma unroll
            for (int nb = 0; nb < 4; nb++) {
                const uint32_t boff = SWZ128((wn + nb * 16 + brow) * 128 + kb + bcolL);
                uint32_t bh[4], bl[4];
                ldm_x4(bh, stBh[s] + boff);
                ldm_x4(bl, stBl[s] + boff);
                #pragma unroll
                for (int mi = 0; mi < 2; mi++) {
                    mma_bf16(acc[mi][nb * 2 + 0], af[mi], bh[0], bh[1]);
                    mma_bf16(acc[mi][nb * 2 + 1], af[mi], bh[2], bh[3]);
                    mma_bf16(acc[mi][nb * 2 + 0], af[mi], bl[0], bl[1]);
                    mma_bf16(acc[mi][nb * 2 + 1], af[mi], bl[2], bl[3]);
                }
            }
        }
        __syncthreads();

        if (k + 2 < N_CHUNK) {
            const int k0 = (k + 2) * 64;
            copy_tile(stA[s], g_spkb, m0, k0, tid);
            copy_tile(stBh[s], g_WinHi, n0, k0, tid);
            copy_tile(stBl[s], g_WinLo, n0, k0, tid);
            CP_COMMIT();
        }
    }

    const int r0 = lane >> 2;
    const int c0 = (lane & 3) * 2;
    #pragma unroll
    for (int mi = 0; mi < 2; mi++) {
        #pragma unroll
        for (int nj = 0; nj < 8; nj++) {
            const int row = m0 + wm + mi * 16 + r0;
            const int col = n0 + wn + nj * 8 + c0;
            float* base = &g_Iin[(size_t)row * HID + col];
            *(float2*)base             = make_float2(acc[mi][nj][0], acc[mi][nj][1]);
            *(float2*)(base + 8 * HID) = make_float2(acc[mi][nj][2], acc[mi][nj][3]);
        }
    }
}

// ---------------- HMMA persistent clustered scan ----------------
// Cluster of 4 CTAs; 8 batch rows per cluster (M padded to 16); 256 h per CTA.
// Phase A: U[16x64] = th[16x256] @ poutT  (warps: 4 n16-cols x 2 k128-halves)
// Phase B: rec[16x256] = U[16x64] @ Wpl^T (warps: 8 x n32)
#define CLUSTER_N   4
#define ROWS_PER_CL 8
#define H_PER_CTA   256
#define NCTAS       128

#define L_OFF_POUT  0                       // bf16 [4 chunks][64 p][64 h] 32KB (SW128)
#define L_OFF_WPL   32768                   // bf16 [256 h][64 p] 32KB (SW128)
#define L_OFF_TH    65536                   // bf16 [4 chunks][16 r][64 h] 8KB (SW128)
#define L_OFF_U     73728                   // bf16 [16 r][64 p] 2KB (SW128)
#define L_OFF_UPART 75776                   // f32 [2 kg][8 r][64 p] 4KB
#define L_OFF_MBOX  79872                   // f32 [2 buf][4 rank][8 r][64 p] 16KB
#define L_SM_TOTAL  96256

__global__ void __cluster_dims__(CLUSTER_N, 1, 1) __launch_bounds__(256, 1)
loop_kernel(const float* __restrict__ pin, const float* __restrict__ pout,
            const float* __restrict__ l) {
    extern __shared__ char smraw[];
    const uint32_t sb = smem_u32(smraw);

    cg::cluster_group cl = cg::this_cluster();
    const int rank = cl.block_rank();
    const int cidx = blockIdx.x / CLUSTER_N;
    const int b0   = cidx * ROWS_PER_CL;
    const int H0   = rank * H_PER_CTA;
    const int tid  = threadIdx.x;
    const int wid  = tid >> 5;
    const int lane = tid & 31;

    // ---- weights -> SMEM (bf16, SW128) ----
    for (int i = tid; i < H_PER_CTA * P_DIM; i += 256) {
        int hl = i >> 6;            // 0..255
        int p  = i & 63;
        float pv = pout[(size_t)(H0 + hl) * P_DIM + p];
        *(__nv_bfloat16*)(smraw + L_OFF_POUT + (hl >> 6) * 8192
                          + SWZ128(p * 128 + (hl & 63) * 2)) = __float2bfloat16(pv);
        float wv = pin[(size_t)(H0 + hl) * P_DIM + p] * l[p];
        *(__nv_bfloat16*)(smraw + L_OFF_WPL + SWZ128(hl * 128 + p * 2)) = __float2bfloat16(wv);
    }
    // zero th (8KB) + U (2KB)
    for (int i = tid; i < (8192 + 2048) / 4; i += 256)
        ((uint32_t*)(smraw + L_OFF_TH))[i] = 0;

    // ---- per-lane constants ----
    const int kg   = wid >> 2;          // phase A k-half
    const int wn16 = (wid & 3) * 16;    // phase A n16 (p cols)
    const int aRow = lane & 15;
    const int aCol = (lane >> 4) << 4;
    const int bRow = (lane & 7) + ((lane >> 4) << 3);
    const int bCol = ((lane >> 3) & 1) << 4;
    const int r    = lane >> 2;         // batch row 0..7
    const int c2   = (lane & 3) * 2;

    // exchange indexing (per thread)
    const int r_e  = tid >> 5;          // 0..7
    const int pp_e = (tid & 31) * 2;    // 0..62
    float* mboxLocal = (float*)(smraw + L_OFF_MBOX);
    float* peerMb[CLUSTER_N];
    #pragma unroll
    for (int rk = 0; rk < CLUSTER_N; rk++)
        peerMb[rk] = (float*)cl.map_shared_rank((void*)mboxLocal, rk);

    // ---- persistent state ----
    float2 memv[4], rmv[4];
    #pragma unroll
    for (int j = 0; j < 4; j++) { memv[j] = make_float2(0.f, 0.f); rmv[j] = make_float2(-2.f, -2.f); }

    cl.sync();

    for (int t = 0; t < T_STEPS; t++) {
        __syncthreads();                 // th(t-1) visible
        const int buf = t & 1;

        // prefetch Iin[t] (float2 per n8 tile)
        float2 iin[4];
        {
            const size_t base = ((size_t)t * BATCH + b0 + r) * HID + H0 + wid * 32 + c2;
            #pragma unroll
            for (int nb = 0; nb < 2; nb++)
                #pragma unroll
                for (int sub = 0; sub < 2; sub++)
                    iin[nb * 2 + sub] = __ldcs((const float2*)&g_Iin[base + nb * 16 + sub * 8]);
        }

        // ---- phase A: partial U over h-half kg ----
        float accA[2][4] = {{0.f,0.f,0.f,0.f},{0.f,0.f,0.f,0.f}};
        #pragma unroll
        for (int cc = 0; cc < 2; cc++) {
            const int ch = kg * 2 + cc;
            const uint32_t thB = sb + L_OFF_TH + ch * 2048;
            const uint32_t poB = sb + L_OFF_POUT + ch * 8192;
            #pragma unroll
            for (int ks = 0; ks < 4; ks++) {
                const int kb = ks * 32;
                uint32_t af[4], bf[4];
                ldm_x4(af, thB + SWZ128(aRow * 128 + kb + aCol));
                ldm_x4(bf, poB + SWZ128((wn16 + bRow) * 128 + kb + bCol));
                mma_bf16(accA[0], af, bf[0], bf[1]);
                mma_bf16(accA[1], af, bf[2], bf[3]);
            }
        }
        // stage partials (rows 0-7 only: c0,c1)
        {
            float* up = (float*)(smraw + L_OFF_UPART);
            *(float2*)&up[(kg * 8 + r) * 64 + wn16 + 0 + c2] = make_float2(accA[0][0], accA[0][1]);
            *(float2*)&up[(kg * 8 + r) * 64 + wn16 + 8 + c2] = make_float2(accA[1][0], accA[1][1]);
        }
        __syncthreads();

        // pair-sum kg halves, scatter to all ranks' mailboxes
        {
            const float* up = (const float*)(smraw + L_OFF_UPART);
            float v0 = up[r_e * 64 + pp_e]     + up[(8 + r_e) * 64 + pp_e];
            float v1 = up[r_e * 64 + pp_e + 1] + up[(8 + r_e) * 64 + pp_e + 1];
            const int moff = ((buf * CLUSTER_N + rank) * 8 + r_e) * 64 + pp_e;
            #pragma unroll
            for (int rk = 0; rk < CLUSTER_N; rk++)
                *(float2*)&peerMb[rk][moff] = make_float2(v0, v1);
        }
        cl.sync();

        // reduce 4 ranks -> U bf16 tile
        {
            const float* mb = mboxLocal + buf * CLUSTER_N * 8 * 64;
            float s0 = 0.f, s1 = 0.f;
            #pragma unroll
            for (int rk = 0; rk < CLUSTER_N; rk++) {
                s0 += mb[(rk * 8 + r_e) * 64 + pp_e];
                s1 += mb[(rk * 8 + r_e) * 64 + pp_e + 1];
            }
            *(__nv_bfloat162*)(smraw + L_OFF_U + SWZ128(r_e * 128 + pp_e * 2)) =
                __floats2bfloat162_rn(s0, s1);
        }
        __syncthreads();

        // ---- phase B: rec[16 x 256], warp covers n32 = wid*32 ----
        float accB[2][2][4];
        #pragma unroll
        for (int nb = 0; nb < 2; nb++)
            #pragma unroll
            for (int sub = 0; sub < 2; sub++)
                #pragma unroll
                for (int q = 0; q < 4; q++) accB[nb][sub][q] = 0.f;

        const uint32_t uB = sb + L_OFF_U;
        const uint32_t wB = sb + L_OFF_WPL;
        #pragma unroll
        for (int ks = 0; ks < 4; ks++) {
            const int kb = ks * 32;
            uint32_t af[4];
            ldm_x4(af, uB + SWZ128(aRow * 128 + kb + aCol));
            #pragma unroll
            for (int nb = 0; nb < 2; nb++) {
                uint32_t bf[4];
                ldm_x4(bf, wB + SWZ128((wid * 32 + nb * 16 + bRow) * 128 + kb + bCol));
                mma_bf16(accB[nb][0], af, bf[0], bf[1]);
                mma_bf16(accB[nb][1], af, bf[2], bf[3]);
            }
        }

        // ---- epilogue: state update + th(t) bf16 ----
        #pragma unroll
        for (int nb = 0; nb < 2; nb++) {
            #pragma unroll
            for (int sub = 0; sub < 2; sub++) {
                const int j  = nb * 2 + sub;
                const int hc = wid * 32 + nb * 16 + sub * 8 + c2;   // local h (even)
                float m0 = (iin[j].x + accB[nb][sub][0] - memv[j].x) * ALPHA;
                float m1 = (iin[j].y + accB[nb][sub][1] - memv[j].y) * ALPHA;
                memv[j].x = m0;  memv[j].y = m1;
                float tv0 = tanhf(m0), tv1 = tanhf(m1);
                rmv[j].x = fmaxf(rmv[j].x, tv0);
                rmv[j].y = fmaxf(rmv[j].y, tv1);
                *(__nv_bfloat162*)(smraw + L_OFF_TH + (hc >> 6) * 2048
                                   + SWZ128(r * 128 + (hc & 63) * 2)) =
                    __floats2bfloat162_rn(tv0, tv1);
            }
        }
    }

    // ---- write running max ----
    #pragma unroll
    for (int nb = 0; nb < 2; nb++)
        #pragma unroll
        for (int sub = 0; sub < 2; sub++) {
            const int j  = nb * 2 + sub;
            const int hc = wid * 32 + nb * 16 + sub * 8 + c2;
            *(float2*)&g_rm[(size_t)(b0 + r) * HID + H0 + hc] = rmv[j];
        }
}

// ---------------- readout ----------------
__global__ void readout_kernel(const float* __restrict__ Wout, float* __restrict__ out) {
    const int b    = blockIdx.x;
    const int lane = threadIdx.x;
    float pacc[OUTD];
    #pragma unroll
    for (int o = 0; o < OUTD; o++) pacc[o] = 0.0f;

    for (int h = lane; h < HID; h += 32) {
        float r = g_rm[(size_t)b * HID + h];
        #pragma unroll
        for (int o = 0; o < OUTD; o++) pacc[o] = fmaf(r, Wout[o * HID + h], pacc[o]);
    }
    #pragma unroll
    for (int o = 0; o < OUTD; o++) {
        #pragma unroll
        for (int off = 16; off > 0; off >>= 1)
            pacc[o] += __shfl_down_sync(0xffffffffu, pacc[o], off);
    }
    if (lane == 0) {
        float mx = pacc[0];
        #pragma unroll
        for (int o = 1; o < OUTD; o++) mx = fmaxf(mx, pacc[o]);
        float e[OUTD], sum = 0.0f;
        #pragma unroll
        for (int o = 0; o < OUTD; o++) { e[o] = expf(pacc[o] - mx); sum += e[o]; }
        float inv = 1.0f / sum;
        #pragma unroll
        for (int o = 0; o < OUTD; o++) out[b * OUTD + o] = e[o] * inv;
    }
}

// ---------------- launch ----------------
extern "C" void kernel_launch(void* const* d_in, const int* in_sizes, int n_in,
                              void* d_out, int out_size) {
    const float* spk  = (const float*)d_in[0];
    const float* Win  = (const float*)d_in[1];
    const float* Wout = (const float*)d_in[2];
    const float* pin  = (const float*)d_in[3];
    const float* pout = (const float*)d_in[4];
    const float* l    = (const float*)d_in[5];
    float* out = (float*)d_out;

    cudaFuncSetAttribute(gemm_mma_kernel, cudaFuncAttributeMaxDynamicSharedMemorySize, SM_TOTAL);
    cudaFuncSetAttribute(loop_kernel, cudaFuncAttributeMaxDynamicSharedMemorySize, L_SM_TOTAL);

    {
        int n = M_TOT * (K_PAD / 8);
        prep_spk_kernel<<<(n + 255) / 256, 256>>>(spk);
    }
    {
        int n = HID * (K_PAD / 8);
        prep_win_kernel<<<(n + 255) / 256, 256>>>(Win);
    }
    gemm_mma_kernel<<<dim3(HID / 128, M_TOT / 128), 256, SM_TOTAL>>>();
    loop_kernel<<<NCTAS, 256, L_SM_TOTAL>>>(pin, pout, l);
    readout_kernel<<<BATCH, 32>>>(Wout, out);
}